// round 2
// baseline (speedup 1.0000x reference)
#include <cuda_runtime.h>
#include <cstdint>
#include <cstddef>

// ============================================================================
// WeaveLayer: X[1024,64], E[1024,1024,64], A[1024,1024] (0/1 int32),
// We[192,64], be[64], Wn[128,64], bn[64]
//   h = E@We_E + (X@We_Xi)[i] + (X@We_Xj)[j] + be
//   E_new = relu(h) * A ;  E_agg[i] = sum_j E_new[i,j]
//   X_new = relu(X@Wn_X + E_agg@Wn_E + bn)
// Output: X_new (65536 f32) then E_new (67108864 f32), concatenated.
//
// Engine: mma.sync.m16n8k8 tf32 (sm_80+ — the build targets compute_100
// WITHOUT the 'a' suffix, so tcgen05 is unavailable).
// ============================================================================

#define NN 1024
#define FF 64

// __device__ scratch (allocation-free rule)
__device__ float g_XiB[NN * FF];            // X@We_Xi + be
__device__ float g_XjV[NN * FF];            // X@We_Xj
__device__ float g_Bimg[64 * 72];           // tf32-converted We_E^T padded to 72
__device__ float g_part[NN * 8 * FF];       // per (i, j-tile) partial E_agg

// ---------------------------------------------------------------------------
static __device__ __forceinline__ uint32_t f2tf32(float x) {
    uint32_t r;
    asm("cvt.rna.tf32.f32 %0, %1;" : "=r"(r) : "f"(x));
    return r;
}

static __device__ __forceinline__ void mma16n8k8(float* c, const uint32_t* a,
                                                 const uint32_t* b) {
    asm volatile(
        "mma.sync.aligned.m16n8k8.row.col.f32.tf32.tf32.f32 "
        "{%0,%1,%2,%3}, {%4,%5,%6,%7}, {%8,%9}, {%0,%1,%2,%3};"
        : "+f"(c[0]), "+f"(c[1]), "+f"(c[2]), "+f"(c[3])
        : "r"(a[0]), "r"(a[1]), "r"(a[2]), "r"(a[3]), "r"(b[0]), "r"(b[1]));
}

// ---------------------------------------------------------------------------
// Kernel 1: XiB = X@We_Xi + be, XjV = X@We_Xj, and tf32 B image (padded 72)
// grid = 17 CTAs x 256 threads. CTA 16 builds the B image.
// ---------------------------------------------------------------------------
__global__ void __launch_bounds__(256)
k_prep(const float* __restrict__ X, const float* __restrict__ We,
       const float* __restrict__ be) {
    __shared__ float Xs[4096];
    __shared__ float Ws[4096];
    __shared__ float bes[64];
    const int b = blockIdx.x, t = threadIdx.x;

    if (b == 16) {
        // Bimg[k][n] = tf32(We_E[k][n]); stride 72 (72 mod 32 == 8 -> B-frag
        // LDS banks = 8k+n, conflict-free)
        for (int idx = t; idx < 4096; idx += 256) {
            int k = idx >> 6, n = idx & 63;
            g_Bimg[k * 72 + n] = __uint_as_float(f2tf32(We[k * 64 + n]));
        }
        return;
    }

    const int r0 = b * 64;
    for (int idx = t; idx < 4096; idx += 256) Xs[idx] = X[r0 * 64 + idx];
    for (int idx = t; idx < 4096; idx += 256) Ws[idx] = We[4096 + idx];  // We_Xi
    if (t < 64) bes[t] = be[t];
    __syncthreads();

    const int r = t >> 2, og = (t & 3) * 16;
    float acc[16];
#pragma unroll
    for (int q = 0; q < 16; ++q) acc[q] = bes[og + q];
    for (int k = 0; k < 64; ++k) {
        float v = Xs[r * 64 + k];
#pragma unroll
        for (int q = 0; q < 16; ++q) acc[q] += v * Ws[k * 64 + og + q];
    }
#pragma unroll
    for (int q = 0; q < 16; ++q) g_XiB[(r0 + r) * 64 + og + q] = acc[q];

    __syncthreads();
    for (int idx = t; idx < 4096; idx += 256) Ws[idx] = We[8192 + idx];  // We_Xj
    __syncthreads();

#pragma unroll
    for (int q = 0; q < 16; ++q) acc[q] = 0.f;
    for (int k = 0; k < 64; ++k) {
        float v = Xs[r * 64 + k];
#pragma unroll
        for (int q = 0; q < 16; ++q) acc[q] += v * Ws[k * 64 + og + q];
    }
#pragma unroll
    for (int q = 0; q < 16; ++q) g_XjV[(r0 + r) * 64 + og + q] = acc[q];
}

// ---------------------------------------------------------------------------
// Kernel 2: main edge kernel. One CTA per (i, 128-wide j-tile). 8192 CTAs.
// SMEM: Es [128][68] f32 (E tile as tf32, then reused as staging),
//       Ws [64][72] f32 (B image), XiB 64 f32, partials 128 f32.
// ---------------------------------------------------------------------------
#define ES_OFF    0
#define WS_OFF    34816
#define XIB_OFF   53248
#define PART_OFF  53504
#define SMEM_MAIN_BYTES 54016

__global__ void __launch_bounds__(128, 4)
k_main(const float* __restrict__ E, const int* __restrict__ A,
       float* __restrict__ outE) {
    extern __shared__ __align__(16) char smem[];
    float*    EsF = (float*)(smem + ES_OFF);
    uint32_t* EsU = (uint32_t*)(smem + ES_OFF);
    uint32_t* WsU = (uint32_t*)(smem + WS_OFF);
    float*    xib = (float*)(smem + XIB_OFF);
    float*    part = (float*)(smem + PART_OFF);

    const int tid = threadIdx.x;
    const int lane = tid & 31, wid = tid >> 5;
    const int tile = blockIdx.x;
    const int i = tile >> 3, jt = tile & 7, j0 = jt << 7;

    // copy tf32 B image (18KB, linear, L2-resident)
    {
        const float4* src = (const float4*)g_Bimg;
        float4* dst = (float4*)(smem + WS_OFF);
        for (int idx = tid; idx < 1152; idx += 128) dst[idx] = src[idx];
    }
    if (tid < 16)
        ((float4*)xib)[tid] = ((const float4*)(g_XiB + i * FF))[tid];

    // load E tile [128 x 64], convert to tf32, store padded (stride 68)
    {
        const float* Esrc = E + ((size_t)i * NN + j0) * FF;
#pragma unroll
        for (int it = 0; it < 16; ++it) {
            int idx = it * 128 + tid;
            int row = idx >> 4, q = idx & 15;
            float4 v = __ldg((const float4*)(Esrc + (size_t)row * FF) + q);
            uint4 u;
            u.x = f2tf32(v.x); u.y = f2tf32(v.y);
            u.z = f2tf32(v.z); u.w = f2tf32(v.w);
            *(uint4*)&EsU[row * 68 + q * 4] = u;
        }
    }
    __syncthreads();

    // ---- tf32 MMA: each warp computes rows [32w, 32w+32) x 64 cols ----
    const int mbase = wid * 32;
    const int arow = mbase + (lane >> 2);
    const int acol = lane & 3;
    const int bk = lane & 3;
    const int bn = lane >> 2;

    float acc[2][8][4];
#pragma unroll
    for (int mi = 0; mi < 2; ++mi)
#pragma unroll
        for (int ni = 0; ni < 8; ++ni)
#pragma unroll
            for (int q = 0; q < 4; ++q) acc[mi][ni][q] = 0.f;

#pragma unroll
    for (int k0 = 0; k0 < 8; ++k0) {
        uint32_t b[8][2];
#pragma unroll
        for (int ni = 0; ni < 8; ++ni) {
            b[ni][0] = WsU[(k0 * 8 + bk) * 72 + ni * 8 + bn];
            b[ni][1] = WsU[(k0 * 8 + bk + 4) * 72 + ni * 8 + bn];
        }
#pragma unroll
        for (int mi = 0; mi < 2; ++mi) {
            uint32_t a[4];
            const int r = arow + mi * 16;
            a[0] = EsU[r * 68 + k0 * 8 + acol];
            a[1] = EsU[(r + 8) * 68 + k0 * 8 + acol];
            a[2] = EsU[r * 68 + k0 * 8 + acol + 4];
            a[3] = EsU[(r + 8) * 68 + k0 * 8 + acol + 4];
#pragma unroll
            for (int ni = 0; ni < 8; ++ni)
                mma16n8k8(acc[mi][ni], a, b[ni]);
        }
    }

    // stage accums back into Es (warp-private rows: no cross-warp hazard)
#pragma unroll
    for (int mi = 0; mi < 2; ++mi) {
        const int r0 = mbase + mi * 16 + (lane >> 2);
#pragma unroll
        for (int ni = 0; ni < 8; ++ni) {
            const int c0 = ni * 8 + 2 * (lane & 3);
            *(float2*)&EsF[r0 * 68 + c0]       = make_float2(acc[mi][ni][0], acc[mi][ni][1]);
            *(float2*)&EsF[(r0 + 8) * 68 + c0] = make_float2(acc[mi][ni][2], acc[mi][ni][3]);
        }
    }
    __syncthreads();

    // ---- epilogue: row m = tid ----
    {
        const int m = tid;
        const float a = (float)__ldg(A + (size_t)i * NN + j0 + m);
        const float4* xjr = (const float4*)(g_XjV + (size_t)(j0 + m) * FF);
        const float4* xb4 = (const float4*)xib;
        float4* orow = (float4*)(outE + ((size_t)i * NN + j0 + m) * FF);
#pragma unroll
        for (int q = 0; q < 16; ++q) {
            float4 v = *(const float4*)&EsF[m * 68 + q * 4];
            float4 xj = xjr[q];
            float4 xb = xb4[q];
            float4 o;
            o.x = fmaxf(v.x + xj.x + xb.x, 0.f) * a;
            o.y = fmaxf(v.y + xj.y + xb.y, 0.f) * a;
            o.z = fmaxf(v.z + xj.z + xb.z, 0.f) * a;
            o.w = fmaxf(v.w + xj.w + xb.w, 0.f) * a;
            *(float4*)&EsF[m * 68 + q * 4] = o;   // restage final value
            orow[q] = o;
        }
    }
    __syncthreads();

    // deterministic column reduction -> E_agg partial for (i, jt)
    {
        const int col = tid & 63, h = tid >> 6;
        float s = 0.f;
#pragma unroll 8
        for (int r = 0; r < 64; ++r)
            s += EsF[(h * 64 + r) * 68 + col];
        part[tid] = s;
    }
    __syncthreads();
    if (tid < 64)
        g_part[((size_t)i * 8 + jt) * 64 + tid] = part[tid] + part[tid + 64];
}

// ---------------------------------------------------------------------------
// Kernel 3: reduce partials -> E_agg, X_new = relu(X@Wn_X + E_agg@Wn_E + bn)
// grid = 16 CTAs x 256 threads, 64 rows per CTA.
// ---------------------------------------------------------------------------
#define SMEM_FINAL_BYTES 65792

__global__ void __launch_bounds__(256)
k_final(const float* __restrict__ X, const float* __restrict__ Wn,
        const float* __restrict__ bn, float* __restrict__ outX) {
    extern __shared__ float fs[];
    float* Wns = fs;             // 8192 floats
    float* Xs  = fs + 8192;      // 4096
    float* Es  = fs + 12288;     // 4096
    float* bns = fs + 16384;     // 64
    const int b = blockIdx.x, t = threadIdx.x;
    const int r0 = b * 64;

    for (int idx = t; idx < 8192; idx += 256) Wns[idx] = Wn[idx];
    for (int idx = t; idx < 4096; idx += 256) Xs[idx] = X[r0 * 64 + idx];
    for (int idx = t; idx < 4096; idx += 256) {
        int r = idx >> 6, c = idx & 63;
        float s = 0.f;
#pragma unroll
        for (int j = 0; j < 8; ++j)
            s += g_part[((size_t)(r0 + r) * 8 + j) * 64 + c];
        Es[idx] = s;
    }
    if (t < 64) bns[t] = bn[t];
    __syncthreads();

    const int r = t >> 2, og = (t & 3) * 16;
    float acc[16];
#pragma unroll
    for (int q = 0; q < 16; ++q) acc[q] = bns[og + q];
    for (int k = 0; k < 64; ++k) {
        float v = Xs[r * 64 + k];
#pragma unroll
        for (int q = 0; q < 16; ++q) acc[q] += v * Wns[k * 64 + og + q];
    }
    for (int k = 0; k < 64; ++k) {
        float v = Es[r * 64 + k];
#pragma unroll
        for (int q = 0; q < 16; ++q) acc[q] += v * Wns[(64 + k) * 64 + og + q];
    }
#pragma unroll
    for (int q = 0; q < 16; ++q)
        outX[(r0 + r) * 64 + og + q] = fmaxf(acc[q], 0.f);
}

// ---------------------------------------------------------------------------
extern "C" void kernel_launch(void* const* d_in, const int* in_sizes, int n_in,
                              void* d_out, int out_size) {
    const float* X  = (const float*)d_in[0];
    const float* E  = (const float*)d_in[1];
    const int*   A  = (const int*)d_in[2];
    const float* We = (const float*)d_in[3];
    const float* be = (const float*)d_in[4];
    const float* Wn = (const float*)d_in[5];
    const float* bn = (const float*)d_in[6];
    float* out = (float*)d_out;

    (void)in_sizes; (void)n_in; (void)out_size;

    cudaFuncSetAttribute(k_main, cudaFuncAttributeMaxDynamicSharedMemorySize,
                         SMEM_MAIN_BYTES);
    cudaFuncSetAttribute(k_final, cudaFuncAttributeMaxDynamicSharedMemorySize,
                         SMEM_FINAL_BYTES);

    k_prep<<<17, 256>>>(X, We, be);
    k_main<<<8192, 128, SMEM_MAIN_BYTES>>>(E, A, out + NN * FF);
    k_final<<<16, 256, SMEM_FINAL_BYTES>>>(X, Wn, bn, out);
}

// round 3
// speedup vs baseline: 1.2548x; 1.2548x over previous
#include <cuda_runtime.h>
#include <cstdint>
#include <cstddef>

// ============================================================================
// WeaveLayer on sm_100 (no 'a' features): mma.sync m16n8k8 tf32 engine.
//   h = E@We_E + (X@We_Xi)[i] + (X@We_Xj)[j] + be
//   E_new = relu(h)*A ; E_agg[i] = sum_j E_new[i,j]
//   X_new = relu(X@Wn_X + E_agg@Wn_E + bn)
// Output: X_new (65536 f32) then E_new (67108864 f32).
// ============================================================================

#define NN 1024
#define FF 64

__device__ float g_XiB[NN * FF];       // X@We_Xi + be
__device__ float g_XjV[NN * FF];       // X@We_Xj
__device__ float g_Bfrag[64 * 64];     // mma-fragment-ordered tf32 We_E
__device__ float g_part[NN * 8 * FF];  // per (i, j-tile) partial E_agg

// ---------------------------------------------------------------------------
static __device__ __forceinline__ uint32_t smem_u32(const void* p) {
    uint32_t a;
    asm("{ .reg .u64 t; cvta.to.shared.u64 t, %1; cvt.u32.u64 %0, t; }"
        : "=r"(a) : "l"(p));
    return a;
}
static __device__ __forceinline__ uint32_t f2tf32(float x) {
    uint32_t r;
    asm("cvt.rna.tf32.f32 %0, %1;" : "=r"(r) : "f"(x));
    return r;
}
static __device__ __forceinline__ void mma16n8k8(float* c, const uint32_t* a,
                                                 const uint32_t* b) {
    asm volatile(
        "mma.sync.aligned.m16n8k8.row.col.f32.tf32.tf32.f32 "
        "{%0,%1,%2,%3}, {%4,%5,%6,%7}, {%8,%9}, {%0,%1,%2,%3};"
        : "+f"(c[0]), "+f"(c[1]), "+f"(c[2]), "+f"(c[3])
        : "r"(a[0]), "r"(a[1]), "r"(a[2]), "r"(a[3]), "r"(b[0]), "r"(b[1]));
}
static __device__ __forceinline__ void cp_async16(uint32_t dst, const void* src) {
    asm volatile("cp.async.cg.shared.global [%0], [%1], 16;"
                 :: "r"(dst), "l"(src) : "memory");
}
#define CP_COMMIT() asm volatile("cp.async.commit_group;" ::: "memory")
#define CP_WAIT(n)  asm volatile("cp.async.wait_group %0;" :: "n"(n) : "memory")

// ---------------------------------------------------------------------------
// Kernel 1: XiB/XjV (fused) + B fragment image. grid = 65 x 256.
// ---------------------------------------------------------------------------
__global__ void __launch_bounds__(256)
k_prep(const float* __restrict__ X, const float* __restrict__ We,
       const float* __restrict__ be) {
    const int b = blockIdx.x, t = threadIdx.x;

    if (b == 64) {
        // g_Bfrag[(k0*8+ni)*64 + lane*2 + h] = tf32(We_E[k0*8+bk+4h][ni*8+bn])
        const int lane = t & 31, grp = t >> 5;
        const int bk = lane & 3, bn = lane >> 2;
        for (int f = grp; f < 64; f += 8) {
            const int k0 = f >> 3, ni = f & 7;
            g_Bfrag[f * 64 + lane * 2 + 0] =
                __uint_as_float(f2tf32(We[(k0 * 8 + bk) * 64 + ni * 8 + bn]));
            g_Bfrag[f * 64 + lane * 2 + 1] =
                __uint_as_float(f2tf32(We[(k0 * 8 + bk + 4) * 64 + ni * 8 + bn]));
        }
        return;
    }

    __shared__ float Ws[8192];   // We_Xi (0..4095), We_Xj (4096..8191)
    __shared__ float Xs[1024];
    __shared__ float bes[64];
    const int r0 = b * 16;

    for (int idx = t; idx < 8192; idx += 256) Ws[idx] = We[4096 + idx];
    for (int idx = t; idx < 1024; idx += 256) Xs[idx] = X[r0 * 64 + idx];
    if (t < 64) bes[t] = be[t];
    __syncthreads();

    const int r = t >> 4, og = (t & 15) * 4;
    float ai[4], aj[4];
#pragma unroll
    for (int q = 0; q < 4; ++q) { ai[q] = bes[og + q]; aj[q] = 0.f; }
#pragma unroll 8
    for (int k = 0; k < 64; ++k) {
        const float v = Xs[r * 64 + k];
        const float4 wi = *(const float4*)&Ws[k * 64 + og];
        const float4 wj = *(const float4*)&Ws[4096 + k * 64 + og];
        ai[0] += v * wi.x; ai[1] += v * wi.y; ai[2] += v * wi.z; ai[3] += v * wi.w;
        aj[0] += v * wj.x; aj[1] += v * wj.y; aj[2] += v * wj.z; aj[3] += v * wj.w;
    }
    *(float4*)&g_XiB[(r0 + r) * 64 + og] = make_float4(ai[0], ai[1], ai[2], ai[3]);
    *(float4*)&g_XjV[(r0 + r) * 64 + og] = make_float4(aj[0], aj[1], aj[2], aj[3]);
}

// ---------------------------------------------------------------------------
// Kernel 2: edge kernel. 1024 persistent CTAs (one i-row), 8 j-tiles each,
// cp.async double-buffered. SMEM layout (bytes):
//   ES0 0..34816, ES1 34816..69632  : E tile [128][68] f32 (raw; also staging)
//   BF  69632..86016                : B fragments 16KB
//   XIB 86016..86272, PART 86272..86784
// ---------------------------------------------------------------------------
#define ES_SZ    34816
#define BF_OFF   69632
#define XIB_OFF  86016
#define PART_OFF 86272
#define SMEM_MAIN_BYTES 86784

__global__ void __launch_bounds__(128, 2)
k_main(const float* __restrict__ E, const int* __restrict__ A,
       float* __restrict__ outE) {
    extern __shared__ __align__(16) char smem[];
    const uint32_t sbase = smem_u32(smem);
    float*    BFs  = (float*)(smem + BF_OFF);
    float*    xib  = (float*)(smem + XIB_OFF);
    float*    part = (float*)(smem + PART_OFF);

    const int tid = threadIdx.x;
    const int lane = tid & 31, wid = tid >> 5;
    const int i = blockIdx.x;

    const float* Erow = E + (size_t)i * NN * FF;
    const int ldrow = tid >> 4, ldq = tid & 15;  // this thread's copy slots

    // prologue: prefetch tile 0 into buffer 0
    {
        const float* src = Erow + (size_t)ldrow * FF + ldq * 4;
        uint32_t dst = sbase + ldrow * 272 + ldq * 16;
#pragma unroll
        for (int it = 0; it < 16; ++it)
            cp_async16(dst + it * 8 * 272, src + (size_t)it * 8 * FF);
        CP_COMMIT();
    }
    // B fragments + XiB (L2-resident, tiny)
    {
        const float4* src = (const float4*)g_Bfrag;
        float4* dst = (float4*)BFs;
#pragma unroll
        for (int it = 0; it < 8; ++it) dst[it * 128 + tid] = src[it * 128 + tid];
        if (tid < 16)
            ((float4*)xib)[tid] = ((const float4*)(g_XiB + i * FF))[tid];
    }

    const int mbase = wid * 32;
    const int arow0 = mbase + (lane >> 2);
    const int acol = lane & 3;

    for (int jt = 0; jt < 8; ++jt) {
        const int j0 = jt << 7;
        float*    EsF = (float*)(smem + (jt & 1) * ES_SZ);
        uint32_t  esb = sbase + (jt & 1) * ES_SZ;

        // prefetch next tile into the other buffer
        if (jt < 7) {
            const float* src = Erow + ((size_t)(j0 + 128 + ldrow)) * FF + ldq * 4;
            uint32_t dst = sbase + ((jt + 1) & 1) * ES_SZ + ldrow * 272 + ldq * 16;
#pragma unroll
            for (int it = 0; it < 16; ++it)
                cp_async16(dst + it * 8 * 272, src + (size_t)it * 8 * FF);
            CP_COMMIT();
            CP_WAIT(1);
        } else {
            CP_WAIT(0);
        }
        __syncthreads();   // current tile resident

        // ---- MMA: warp w -> rows [32w, 32w+32) x 64 cols ----
        float acc[2][8][4];
#pragma unroll
        for (int mi = 0; mi < 2; ++mi)
#pragma unroll
            for (int ni = 0; ni < 8; ++ni)
#pragma unroll
                for (int q = 0; q < 4; ++q) acc[mi][ni][q] = 0.f;

#pragma unroll
        for (int k0 = 0; k0 < 8; ++k0) {
            uint2 bb[8];
#pragma unroll
            for (int ni = 0; ni < 8; ++ni)
                bb[ni] = *(const uint2*)&BFs[(k0 * 8 + ni) * 64 + lane * 2];
#pragma unroll
            for (int mi = 0; mi < 2; ++mi) {
                const int r = arow0 + mi * 16;
                uint32_t a[4];
                a[0] = f2tf32(EsF[r * 68 + k0 * 8 + acol]);
                a[1] = f2tf32(EsF[(r + 8) * 68 + k0 * 8 + acol]);
                a[2] = f2tf32(EsF[r * 68 + k0 * 8 + acol + 4]);
                a[3] = f2tf32(EsF[(r + 8) * 68 + k0 * 8 + acol + 4]);
#pragma unroll
                for (int ni = 0; ni < 8; ++ni)
                    mma16n8k8(acc[mi][ni], a, (const uint32_t*)&bb[ni]);
            }
        }

        // stage accums into own warp's rows (no cross-warp hazard)
#pragma unroll
        for (int mi = 0; mi < 2; ++mi) {
            const int r0s = mbase + mi * 16 + (lane >> 2);
#pragma unroll
            for (int ni = 0; ni < 8; ++ni) {
                const int c0 = ni * 8 + 2 * (lane & 3);
                *(float2*)&EsF[r0s * 68 + c0] =
                    make_float2(acc[mi][ni][0], acc[mi][ni][1]);
                *(float2*)&EsF[(r0s + 8) * 68 + c0] =
                    make_float2(acc[mi][ni][2], acc[mi][ni][3]);
            }
        }
        __syncthreads();

        // ---- epilogue: row m = tid ----
        {
            const int m = tid;
            const float a = (float)__ldg(A + (size_t)i * NN + j0 + m);
            const float4* xjr = (const float4*)(g_XjV + (size_t)(j0 + m) * FF);
            const float4* xb4 = (const float4*)xib;
            float4* orow = (float4*)(outE + ((size_t)i * NN + j0 + m) * FF);
#pragma unroll
            for (int q = 0; q < 16; ++q) {
                float4 v = *(const float4*)&EsF[m * 68 + q * 4];
                float4 xj = xjr[q];
                float4 xb = xb4[q];
                float4 o;
                o.x = fmaxf(v.x + xj.x + xb.x, 0.f) * a;
                o.y = fmaxf(v.y + xj.y + xb.y, 0.f) * a;
                o.z = fmaxf(v.z + xj.z + xb.z, 0.f) * a;
                o.w = fmaxf(v.w + xj.w + xb.w, 0.f) * a;
                *(float4*)&EsF[m * 68 + q * 4] = o;  // restage final value
                orow[q] = o;
            }
        }
        __syncthreads();

        // deterministic column reduction -> partial for (i, jt)
        {
            const int col = tid & 63, h = tid >> 6;
            float s = 0.f;
#pragma unroll 8
            for (int r = 0; r < 64; ++r)
                s += EsF[(h * 64 + r) * 68 + col];
            part[tid] = s;
        }
        __syncthreads();
        if (tid < 64)
            g_part[((size_t)i * 8 + jt) * 64 + tid] = part[tid] + part[tid + 64];
        __syncthreads();
    }
}

// ---------------------------------------------------------------------------
// Kernel 3: E_agg + node GEMM. grid = 64 x 256, 16 rows per CTA.
// ---------------------------------------------------------------------------
__global__ void __launch_bounds__(256)
k_final(const float* __restrict__ X, const float* __restrict__ Wn,
        const float* __restrict__ bn, float* __restrict__ outX) {
    __shared__ float Wns[8192];
    __shared__ float Xs[1024];
    __shared__ float Es[1024];
    __shared__ float bns[64];
    const int b = blockIdx.x, t = threadIdx.x;
    const int r0 = b * 16;

    for (int idx = t; idx < 8192; idx += 256) Wns[idx] = Wn[idx];
    for (int idx = t; idx < 1024; idx += 256) Xs[idx] = X[r0 * 64 + idx];
    for (int idx = t; idx < 1024; idx += 256) {
        const int r = idx >> 6, c = idx & 63;
        float s = 0.f;
#pragma unroll
        for (int j = 0; j < 8; ++j)
            s += g_part[((size_t)(r0 + r) * 8 + j) * 64 + c];
        Es[idx] = s;
    }
    if (t < 64) bns[t] = bn[t];
    __syncthreads();

    const int r = t >> 4, og = (t & 15) * 4;
    float acc[4];
#pragma unroll
    for (int q = 0; q < 4; ++q) acc[q] = bns[og + q];
#pragma unroll 8
    for (int k = 0; k < 64; ++k) {
        const float v = Xs[r * 64 + k];
        const float4 w = *(const float4*)&Wns[k * 64 + og];
        acc[0] += v * w.x; acc[1] += v * w.y; acc[2] += v * w.z; acc[3] += v * w.w;
    }
#pragma unroll 8
    for (int k = 0; k < 64; ++k) {
        const float v = Es[r * 64 + k];
        const float4 w = *(const float4*)&Wns[(64 + k) * 64 + og];
        acc[0] += v * w.x; acc[1] += v * w.y; acc[2] += v * w.z; acc[3] += v * w.w;
    }
    *(float4*)&outX[(r0 + r) * 64 + og] =
        make_float4(fmaxf(acc[0], 0.f), fmaxf(acc[1], 0.f),
                    fmaxf(acc[2], 0.f), fmaxf(acc[3], 0.f));
}

// ---------------------------------------------------------------------------
extern "C" void kernel_launch(void* const* d_in, const int* in_sizes, int n_in,
                              void* d_out, int out_size) {
    const float* X  = (const float*)d_in[0];
    const float* E  = (const float*)d_in[1];
    const int*   A  = (const int*)d_in[2];
    const float* We = (const float*)d_in[3];
    const float* be = (const float*)d_in[4];
    const float* Wn = (const float*)d_in[5];
    const float* bn = (const float*)d_in[6];
    float* out = (float*)d_out;

    (void)in_sizes; (void)n_in; (void)out_size;

    cudaFuncSetAttribute(k_main, cudaFuncAttributeMaxDynamicSharedMemorySize,
                         SMEM_MAIN_BYTES);

    k_prep<<<65, 256>>>(X, We, be);
    k_main<<<1024, 128, SMEM_MAIN_BYTES>>>(E, A, out + NN * FF);
    k_final<<<64, 256>>>(X, Wn, bn, out);
}

// round 4
// speedup vs baseline: 2.5133x; 2.0030x over previous
#include <cuda_runtime.h>
#include <cstdint>
#include <cstddef>

// ============================================================================
// WeaveLayer on sm_100 (no 'a' features): mma.sync m16n8k8 tf32 engine.
//   h = E@We_E + (X@We_Xi)[i] + (X@We_Xj)[j] + be
//   E_new = relu(h)*A ; E_agg[i] = sum_j E_new[i,j]
//   X_new = relu(X@Wn_X + E_agg@Wn_E + bn)
// Output: X_new (65536 f32) then E_new (67108864 f32).
// R4: register epilogue + shfl reduction, 1 tile/CTA, 4 CTAs/SM.
// ============================================================================

#define NN 1024
#define FF 64

__device__ float g_XiB[NN * FF];       // X@We_Xi + be
__device__ float g_XjV[NN * FF];       // X@We_Xj
__device__ float g_Bfrag[64 * 64];     // mma-fragment-ordered tf32 We_E
__device__ float g_part[NN * 8 * FF];  // per (i, j-tile) partial E_agg

// ---------------------------------------------------------------------------
static __device__ __forceinline__ uint32_t smem_u32(const void* p) {
    uint32_t a;
    asm("{ .reg .u64 t; cvta.to.shared.u64 t, %1; cvt.u32.u64 %0, t; }"
        : "=r"(a) : "l"(p));
    return a;
}
static __device__ __forceinline__ uint32_t f2tf32(float x) {
    uint32_t r;
    asm("cvt.rna.tf32.f32 %0, %1;" : "=r"(r) : "f"(x));
    return r;
}
static __device__ __forceinline__ void mma16n8k8(float* c, const uint32_t* a,
                                                 const uint32_t* b) {
    asm volatile(
        "mma.sync.aligned.m16n8k8.row.col.f32.tf32.tf32.f32 "
        "{%0,%1,%2,%3}, {%4,%5,%6,%7}, {%8,%9}, {%0,%1,%2,%3};"
        : "+f"(c[0]), "+f"(c[1]), "+f"(c[2]), "+f"(c[3])
        : "r"(a[0]), "r"(a[1]), "r"(a[2]), "r"(a[3]), "r"(b[0]), "r"(b[1]));
}
static __device__ __forceinline__ void cp_async16(uint32_t dst, const void* src) {
    asm volatile("cp.async.cg.shared.global [%0], [%1], 16;"
                 :: "r"(dst), "l"(src) : "memory");
}
#define CP_COMMIT() asm volatile("cp.async.commit_group;" ::: "memory")
#define CP_WAIT(n)  asm volatile("cp.async.wait_group %0;" :: "n"(n) : "memory")

// ---------------------------------------------------------------------------
// Kernel 1: XiB/XjV (fused) + B fragment image. grid = 65 x 256.
// ---------------------------------------------------------------------------
__global__ void __launch_bounds__(256)
k_prep(const float* __restrict__ X, const float* __restrict__ We,
       const float* __restrict__ be) {
    const int b = blockIdx.x, t = threadIdx.x;

    if (b == 64) {
        // g_Bfrag[(k0*8+ni)*64 + lane*2 + h] = tf32(We_E[k0*8+bk+4h][ni*8+bn])
        const int lane = t & 31, grp = t >> 5;
        const int bk = lane & 3, bn = lane >> 2;
        for (int f = grp; f < 64; f += 8) {
            const int k0 = f >> 3, ni = f & 7;
            g_Bfrag[f * 64 + lane * 2 + 0] =
                __uint_as_float(f2tf32(We[(k0 * 8 + bk) * 64 + ni * 8 + bn]));
            g_Bfrag[f * 64 + lane * 2 + 1] =
                __uint_as_float(f2tf32(We[(k0 * 8 + bk + 4) * 64 + ni * 8 + bn]));
        }
        return;
    }

    __shared__ float Ws[8192];   // We_Xi (0..4095), We_Xj (4096..8191)
    __shared__ float Xs[1024];
    __shared__ float bes[64];
    const int r0 = b * 16;

    for (int idx = t; idx < 8192; idx += 256) Ws[idx] = We[4096 + idx];
    for (int idx = t; idx < 1024; idx += 256) Xs[idx] = X[r0 * 64 + idx];
    if (t < 64) bes[t] = be[t];
    __syncthreads();

    const int r = t >> 4, og = (t & 15) * 4;
    float ai[4], aj[4];
#pragma unroll
    for (int q = 0; q < 4; ++q) { ai[q] = bes[og + q]; aj[q] = 0.f; }
#pragma unroll 8
    for (int k = 0; k < 64; ++k) {
        const float v = Xs[r * 64 + k];
        const float4 wi = *(const float4*)&Ws[k * 64 + og];
        const float4 wj = *(const float4*)&Ws[4096 + k * 64 + og];
        ai[0] += v * wi.x; ai[1] += v * wi.y; ai[2] += v * wi.z; ai[3] += v * wi.w;
        aj[0] += v * wj.x; aj[1] += v * wj.y; aj[2] += v * wj.z; aj[3] += v * wj.w;
    }
    *(float4*)&g_XiB[(r0 + r) * 64 + og] = make_float4(ai[0], ai[1], ai[2], ai[3]);
    *(float4*)&g_XjV[(r0 + r) * 64 + og] = make_float4(aj[0], aj[1], aj[2], aj[3]);
}

// ---------------------------------------------------------------------------
// Kernel 2: edge kernel. One CTA per (i, 128-wide j-tile) = 8192 CTAs.
// SMEM: E tile [128][68] f32 at 0..34816, part 1KB at 34816.
// Register-resident epilogue; shfl column reduction. 2 syncthreads total.
// ---------------------------------------------------------------------------
#define PART_OFF 34816
#define SMEM_MAIN_BYTES 35840

__global__ void __launch_bounds__(128, 4)
k_main(const float* __restrict__ E, const int* __restrict__ A,
       float* __restrict__ outE) {
    extern __shared__ __align__(16) char smem[];
    float* EsF  = (float*)smem;
    float* part = (float*)(smem + PART_OFF);
    const uint32_t sbase = smem_u32(smem);

    const int tid = threadIdx.x;
    const int lane = tid & 31, wid = tid >> 5;
    const int tile = blockIdx.x;
    const int i = tile >> 3, jt = tile & 7, j0 = jt << 7;

    // prefetch E tile [128 x 64] into padded smem (stride 68 floats)
    {
        const int ldrow = tid >> 4, ldq = tid & 15;
        const float* src = E + ((size_t)i * NN + j0 + ldrow) * FF + ldq * 4;
        const uint32_t dst = sbase + ldrow * 272 + ldq * 16;
#pragma unroll
        for (int it = 0; it < 16; ++it)
            cp_async16(dst + it * 8 * 272, src + (size_t)it * 8 * FF);
        CP_COMMIT();
    }

    // per-thread constants while the tile is in flight
    const int R0 = wid * 32 + (lane >> 2);   // first of this thread's 4 rows
    const int acol = lane & 3;
    const int c2 = 2 * (lane & 3);

    float xib0[8], xib1[8];
    {
        const float* xb = g_XiB + i * FF;
#pragma unroll
        for (int ni = 0; ni < 8; ++ni) {
            const float2 v = __ldg((const float2*)(xb + ni * 8 + c2));
            xib0[ni] = v.x; xib1[ni] = v.y;
        }
    }
    float am[4];
#pragma unroll
    for (int mi = 0; mi < 2; ++mi) {
        am[mi * 2 + 0] = (float)__ldg(A + (size_t)i * NN + j0 + R0 + mi * 16);
        am[mi * 2 + 1] = (float)__ldg(A + (size_t)i * NN + j0 + R0 + mi * 16 + 8);
    }

    CP_WAIT(0);
    __syncthreads();

    // ---- MMA: warp w -> rows [32w, 32w+32) x 64 cols ----
    float acc[2][8][4];
#pragma unroll
    for (int mi = 0; mi < 2; ++mi)
#pragma unroll
        for (int ni = 0; ni < 8; ++ni)
#pragma unroll
            for (int q = 0; q < 4; ++q) acc[mi][ni][q] = 0.f;

#pragma unroll
    for (int k0 = 0; k0 < 8; ++k0) {
        uint2 bb[8];
#pragma unroll
        for (int ni = 0; ni < 8; ++ni)
            bb[ni] = __ldg((const uint2*)(g_Bfrag + (k0 * 8 + ni) * 64 + lane * 2));
#pragma unroll
        for (int mi = 0; mi < 2; ++mi) {
            const int r = R0 + mi * 16;
            uint32_t a[4];
            a[0] = f2tf32(EsF[r * 68 + k0 * 8 + acol]);
            a[1] = f2tf32(EsF[(r + 8) * 68 + k0 * 8 + acol]);
            a[2] = f2tf32(EsF[r * 68 + k0 * 8 + acol + 4]);
            a[3] = f2tf32(EsF[(r + 8) * 68 + k0 * 8 + acol + 4]);
#pragma unroll
            for (int ni = 0; ni < 8; ++ni)
                mma16n8k8(acc[mi][ni], a, (const uint32_t*)&bb[ni]);
        }
    }

    // ---- register epilogue + column partial sums ----
    float cs0[8], cs1[8];
#pragma unroll
    for (int ni = 0; ni < 8; ++ni) { cs0[ni] = 0.f; cs1[ni] = 0.f; }

    float* obase = outE + ((size_t)i * NN + j0) * FF;
#pragma unroll
    for (int mi = 0; mi < 2; ++mi) {
        const int rA = R0 + mi * 16, rB = rA + 8;
        const float* xjA = g_XjV + (size_t)(j0 + rA) * FF;
        const float* xjB = g_XjV + (size_t)(j0 + rB) * FF;
        const float aA = am[mi * 2 + 0], aB = am[mi * 2 + 1];
#pragma unroll
        for (int ni = 0; ni < 8; ++ni) {
            const int C = ni * 8 + c2;
            const float2 ja = __ldg((const float2*)(xjA + C));
            const float2 jb = __ldg((const float2*)(xjB + C));
            const float o0 = fmaxf(acc[mi][ni][0] + ja.x + xib0[ni], 0.f) * aA;
            const float o1 = fmaxf(acc[mi][ni][1] + ja.y + xib1[ni], 0.f) * aA;
            const float o2 = fmaxf(acc[mi][ni][2] + jb.x + xib0[ni], 0.f) * aB;
            const float o3 = fmaxf(acc[mi][ni][3] + jb.y + xib1[ni], 0.f) * aB;
            *(float2*)(obase + (size_t)rA * FF + C) = make_float2(o0, o1);
            *(float2*)(obase + (size_t)rB * FF + C) = make_float2(o2, o3);
            cs0[ni] += o0 + o2;
            cs1[ni] += o1 + o3;
        }
    }

    // shfl-reduce over the 8 row-groups (lanes differing in bits 2..4)
#pragma unroll
    for (int ni = 0; ni < 8; ++ni) {
#pragma unroll
        for (int ofs = 4; ofs < 32; ofs <<= 1) {
            cs0[ni] += __shfl_xor_sync(0xffffffffu, cs0[ni], ofs);
            cs1[ni] += __shfl_xor_sync(0xffffffffu, cs1[ni], ofs);
        }
    }
    if (lane < 4) {
#pragma unroll
        for (int ni = 0; ni < 8; ++ni)
            *(float2*)&part[wid * 64 + ni * 8 + lane * 2] =
                make_float2(cs0[ni], cs1[ni]);
    }
    __syncthreads();
    if (tid < 64)
        g_part[((size_t)i * 8 + jt) * 64 + tid] =
            (part[tid] + part[64 + tid]) + (part[128 + tid] + part[192 + tid]);
}

// ---------------------------------------------------------------------------
// Kernel 3: E_agg + node GEMM. grid = 64 x 256, 16 rows per CTA.
// ---------------------------------------------------------------------------
__global__ void __launch_bounds__(256)
k_final(const float* __restrict__ X, const float* __restrict__ Wn,
        const float* __restrict__ bn, float* __restrict__ outX) {
    __shared__ float Wns[8192];
    __shared__ float Xs[1024];
    __shared__ float Es[1024];
    __shared__ float bns[64];
    const int b = blockIdx.x, t = threadIdx.x;
    const int r0 = b * 16;

    for (int idx = t; idx < 8192; idx += 256) Wns[idx] = Wn[idx];
    for (int idx = t; idx < 1024; idx += 256) Xs[idx] = X[r0 * 64 + idx];
    for (int idx = t; idx < 1024; idx += 256) {
        const int r = idx >> 6, c = idx & 63;
        float s = 0.f;
#pragma unroll
        for (int j = 0; j < 8; ++j)
            s += g_part[((size_t)(r0 + r) * 8 + j) * 64 + c];
        Es[idx] = s;
    }
    if (t < 64) bns[t] = bn[t];
    __syncthreads();

    const int r = t >> 4, og = (t & 15) * 4;
    float acc[4];
#pragma unroll
    for (int q = 0; q < 4; ++q) acc[q] = bns[og + q];
#pragma unroll 8
    for (int k = 0; k < 64; ++k) {
        const float v = Xs[r * 64 + k];
        const float4 w = *(const float4*)&Wns[k * 64 + og];
        acc[0] += v * w.x; acc[1] += v * w.y; acc[2] += v * w.z; acc[3] += v * w.w;
    }
#pragma unroll 8
    for (int k = 0; k < 64; ++k) {
        const float v = Es[r * 64 + k];
        const float4 w = *(const float4*)&Wns[(64 + k) * 64 + og];
        acc[0] += v * w.x; acc[1] += v * w.y; acc[2] += v * w.z; acc[3] += v * w.w;
    }
    *(float4*)&outX[(r0 + r) * 64 + og] =
        make_float4(fmaxf(acc[0], 0.f), fmaxf(acc[1], 0.f),
                    fmaxf(acc[2], 0.f), fmaxf(acc[3], 0.f));
}

// ---------------------------------------------------------------------------
extern "C" void kernel_launch(void* const* d_in, const int* in_sizes, int n_in,
                              void* d_out, int out_size) {
    const float* X  = (const float*)d_in[0];
    const float* E  = (const float*)d_in[1];
    const int*   A  = (const int*)d_in[2];
    const float* We = (const float*)d_in[3];
    const float* be = (const float*)d_in[4];
    const float* Wn = (const float*)d_in[5];
    const float* bn = (const float*)d_in[6];
    float* out = (float*)d_out;

    (void)in_sizes; (void)n_in; (void)out_size;

    cudaFuncSetAttribute(k_main, cudaFuncAttributeMaxDynamicSharedMemorySize,
                         SMEM_MAIN_BYTES);

    k_prep<<<65, 256>>>(X, We, be);
    k_main<<<8192, 128, SMEM_MAIN_BYTES>>>(E, A, out + NN * FF);
    k_final<<<64, 256>>>(X, Wn, bn, out);
}